// round 7
// baseline (speedup 1.0000x reference)
#include <cuda_runtime.h>
#include <float.h>

// Scratch (allocation-free: __device__ globals). g_hist is zero on first run
// (static init) and re-zeroed by select_kernel after use -> every graph
// replay sees zeros. Deterministic.
__device__ float g_ce[32768];
__device__ int   g_hist[4096];

// ---------------------------------------------------------------------------
// Monotone key transform (order-preserving float -> uint).
// ---------------------------------------------------------------------------
__device__ __forceinline__ unsigned f2key(float f) {
    unsigned b = __float_as_uint(f);
    return (b & 0x80000000u) ? ~b : (b | 0x80000000u);
}
__device__ __forceinline__ float key2f(unsigned k) {
    unsigned b = (k & 0x80000000u) ? (k ^ 0x80000000u) : ~k;
    return __uint_as_float(b);
}

// ---------------------------------------------------------------------------
// Kernel 1: per-row cross entropy + inline target-dtype detection + fused
// global histogram of key bits [31:20]. One warp per row; HBM-bound.
// ---------------------------------------------------------------------------
__global__ void __launch_bounds__(256)
ce_kernel(const float* __restrict__ x,
          const void* __restrict__ tgt,
          int N, int C)
{
    const int row  = blockIdx.x * 8 + (threadIdx.x >> 5);
    const int lane = threadIdx.x & 31;
    if (row >= N) return;

    const float4* rp = reinterpret_cast<const float4*>(x + (size_t)row * C);
    const int C4 = C >> 2;  // 250 for C=1000

    float4 v[8];
#pragma unroll
    for (int i = 0; i < 8; i++) {
        int c = lane + (i << 5);
        if (c < C4) v[i] = rp[c];
        else        v[i] = make_float4(-FLT_MAX, -FLT_MAX, -FLT_MAX, -FLT_MAX);
    }

    // Dtype probe (int64 targets in [0,C) have zero odd 32-bit words; L1-hot).
    const int* tw = reinterpret_cast<const int*>(tgt);
    int hiw = tw[2 * lane + 1];
    bool is64 = __all_sync(0xFFFFFFFFu, hiw == 0);

    float xt = 0.f;
    if (lane == 0) {
        long long t = is64 ? reinterpret_cast<const long long*>(tgt)[row]
                           : (long long)reinterpret_cast<const int*>(tgt)[row];
        if (t < 0)  t = 0;
        if (t >= C) t = C - 1;
        xt = x[(size_t)row * C + (int)t];
    }

    float m = -FLT_MAX;
#pragma unroll
    for (int i = 0; i < 8; i++)
        m = fmaxf(m, fmaxf(fmaxf(v[i].x, v[i].y), fmaxf(v[i].z, v[i].w)));
#pragma unroll
    for (int o = 16; o; o >>= 1)
        m = fmaxf(m, __shfl_xor_sync(0xFFFFFFFFu, m, o));

    float s0 = 0.f, s1 = 0.f, s2 = 0.f, s3 = 0.f;
#pragma unroll
    for (int i = 0; i < 8; i++) {
        s0 += __expf(v[i].x - m);
        s1 += __expf(v[i].y - m);
        s2 += __expf(v[i].z - m);
        s3 += __expf(v[i].w - m);
    }
    float s = (s0 + s1) + (s2 + s3);
#pragma unroll
    for (int o = 16; o; o >>= 1)
        s += __shfl_xor_sync(0xFFFFFFFFu, s, o);

    if (lane == 0) {
        float ce = m + __logf(s) - xt;
        g_ce[row] = ce;
        atomicAdd(&g_hist[f2key(ce) >> 20], 1);
    }
}

// ---------------------------------------------------------------------------
// Warp-cooperative descending scan of a 4096-entry histogram:
// find bucket containing 0-indexed descending rank, return bucket + residual.
// Two redistribution stages keep the serial walk <= 4 iterations.
// Call from warp 0 only.
// ---------------------------------------------------------------------------
__device__ void warp_scan_desc_4096(const int* h, int rank, int& bucket, int& rres)
{
    const unsigned FULL = 0xFFFFFFFFu;
    const int lane = threadIdx.x & 31;

    // Stage 1: 128-entry descending chunks.
    int base = 4095 - lane * 128;
    int csum = 0;
#pragma unroll 16
    for (int i = 0; i < 128; i++) csum += h[base - i];
    int inc = csum;
#pragma unroll
    for (int o = 1; o < 32; o <<= 1) {
        int v = __shfl_up_sync(FULL, inc, o);
        if (lane >= o) inc += v;
    }
    int excl = inc - csum;
    unsigned bal = __ballot_sync(FULL, (rank >= excl) && (rank < excl + csum));
    int hl = __ffs(bal) - 1;
    int rr = rank - __shfl_sync(FULL, excl, hl);
    int hbase = 4095 - hl * 128;

    // Stage 2: 4-entry descending chunks within the chosen 128.
    int b2 = hbase - lane * 4;
    int c2 = h[b2] + h[b2 - 1] + h[b2 - 2] + h[b2 - 3];
    int inc2 = c2;
#pragma unroll
    for (int o = 1; o < 32; o <<= 1) {
        int v = __shfl_up_sync(FULL, inc2, o);
        if (lane >= o) inc2 += v;
    }
    int excl2 = inc2 - c2;
    unsigned bal2 = __ballot_sync(FULL, (rr >= excl2) && (rr < excl2 + c2));
    int hl2 = __ffs(bal2) - 1;
    int rr2 = rr - __shfl_sync(FULL, excl2, hl2);

    // Stage 3: serial walk of <= 4 on the hit lane.
    int bkt = -1;
    if (lane == hl2) {
        int bb = hbase - hl2 * 4;
#pragma unroll
        for (int i = 0; i < 4; i++) {
            int c = h[bb - i];
            if (rr2 < c) { bkt = bb - i; break; }
            rr2 -= c;
        }
    }
    bucket = __shfl_sync(FULL, bkt, hl2);
    rres   = __shfl_sync(FULL, rr2, hl2);
}

// Same idea for a 256-entry histogram (final 8 bits -> exact key).
__device__ void warp_scan_desc_256(const int* h, int rank, int& bucket)
{
    const unsigned FULL = 0xFFFFFFFFu;
    const int lane = threadIdx.x & 31;

    int base = 255 - lane * 8;
    int csum = 0;
#pragma unroll
    for (int i = 0; i < 8; i++) csum += h[base - i];
    int inc = csum;
#pragma unroll
    for (int o = 1; o < 32; o <<= 1) {
        int v = __shfl_up_sync(FULL, inc, o);
        if (lane >= o) inc += v;
    }
    int excl = inc - csum;
    unsigned bal = __ballot_sync(FULL, (rank >= excl) && (rank < excl + csum));
    int hl = __ffs(bal) - 1;
    int rr = rank - __shfl_sync(FULL, excl, hl);

    int bkt = -1;
    if (lane == hl) {
        int bb = 255 - hl * 8;
#pragma unroll
        for (int i = 0; i < 8; i++) {
            int c = h[bb - i];
            if (rr < c) { bkt = bb - i; break; }
            rr -= c;
        }
    }
    bucket = __shfl_sync(FULL, bkt, hl);
}

// ---------------------------------------------------------------------------
// Kernel 2: single CTA, 1024 threads x 32 register-resident keys.
// 3-level histogram drill-down (12+12+8 bits) -> exact lamkey (full 32 bits,
// exact tie semantics of sorted_desc[k]), then masked mean.
// ---------------------------------------------------------------------------
__global__ void __launch_bounds__(1024)
select_mean_kernel(float* __restrict__ out, int N, int k)
{
    const int tid  = threadIdx.x;
    const int lane = tid & 31;
    const int wid  = tid >> 5;

    __shared__ int      s_h1[4096];
    __shared__ int      s_h2[4096];
    __shared__ int      s_h3[256];
    __shared__ int      s_b1;
    __shared__ unsigned s_p24;
    __shared__ unsigned s_lam;
    __shared__ float    s_fsum[32];

    // Copy level-1 histogram to smem; zero level-2/3.
#pragma unroll
    for (int i = 0; i < 4; i++) {
        s_h1[tid + (i << 10)] = g_hist[tid + (i << 10)];
        s_h2[tid + (i << 10)] = 0;
    }
    if (tid < 256) s_h3[tid] = 0;

    // Load keys into registers (g_ce is L2-resident).
    unsigned key[32];
#pragma unroll
    for (int i = 0; i < 32; i++) {
        int idx = tid + (i << 10);
        key[i] = (idx < N) ? f2key(g_ce[idx]) : 0u;  // 0 = smaller than any real key
    }
    __syncthreads();

    // Re-zero g_hist for the next graph replay (g_hist fully consumed above).
#pragma unroll
    for (int i = 0; i < 4; i++) g_hist[tid + (i << 10)] = 0;

    // Level 1: warp 0 finds the 12-bit bucket holding rank k.
    int r1 = 0;
    if (wid == 0) {
        int b1;
        warp_scan_desc_4096(s_h1, k, b1, r1);
        if (lane == 0) s_b1 = b1;
    }
    __syncthreads();
    const unsigned b1 = (unsigned)s_b1;

    // Level 2: histogram of key bits [19:8] among keys with top-12 == b1.
#pragma unroll
    for (int i = 0; i < 32; i++)
        if ((key[i] >> 20) == b1)
            atomicAdd(&s_h2[(key[i] >> 8) & 0xFFFu], 1);
    __syncthreads();

    if (wid == 0) {
        int b2, r2;
        warp_scan_desc_4096(s_h2, r1, b2, r2);
        r1 = r2;  // residual carried in warp 0's registers
        if (lane == 0) s_p24 = (b1 << 12) | (unsigned)b2;
    }
    __syncthreads();
    const unsigned p24 = s_p24;

    // Level 3: histogram of final 8 bits among keys with top-24 == p24.
#pragma unroll
    for (int i = 0; i < 32; i++)
        if ((key[i] >> 8) == p24)
            atomicAdd(&s_h3[key[i] & 0xFFu], 1);
    __syncthreads();

    if (wid == 0) {
        int b3;
        warp_scan_desc_256(s_h3, r1, b3);
        if (lane == 0) s_lam = (p24 << 8) | (unsigned)b3;
    }
    __syncthreads();
    const unsigned lam = s_lam;  // exact key of sorted_desc[k]

    // Masked sum: keep key >= lam (ties kept, matching `ce < lam -> 0`).
    float sum = 0.f;
#pragma unroll
    for (int i = 0; i < 32; i++)
        if (key[i] >= lam) sum += key2f(key[i]);
#pragma unroll
    for (int o = 16; o; o >>= 1)
        sum += __shfl_xor_sync(0xFFFFFFFFu, sum, o);
    if (lane == 0) s_fsum[wid] = sum;
    __syncthreads();

    if (tid == 0) {
        double tot = 0.0;
#pragma unroll
        for (int w = 0; w < 32; w++) tot += (double)s_fsum[w];
        out[0] = (float)(tot / (double)N);
    }
}

// ---------------------------------------------------------------------------
extern "C" void kernel_launch(void* const* d_in, const int* in_sizes, int n_in,
                              void* d_out, int out_size)
{
    int li = 0, ti = 1;
    if (n_in >= 2 && in_sizes[1] > in_sizes[0]) { li = 1; ti = 0; }

    const float* x   = (const float*)d_in[li];
    const void*  tgt = d_in[ti];
    float* out = (float*)d_out;

    const int N = in_sizes[ti];            // 32768
    const int C = in_sizes[li] / N;        // 1000
    const int k = (int)((double)N * 0.3);  // 9830

    const int warps_per_block = 8;
    const int blocks = (N + warps_per_block - 1) / warps_per_block;
    ce_kernel<<<blocks, 256>>>(x, tgt, N, C);

    select_mean_kernel<<<1, 1024>>>(out, N, k);
}

// round 9
// speedup vs baseline: 1.2295x; 1.2295x over previous
#include <cuda_runtime.h>
#include <float.h>

// Scratch for per-sample CE losses (allocation-free: __device__ global).
__device__ float g_ce[32768];

// Monotone key transform (order-preserving float <-> uint).
__device__ __forceinline__ unsigned f2key(float f) {
    unsigned b = __float_as_uint(f);
    return (b & 0x80000000u) ? ~b : (b | 0x80000000u);
}
__device__ __forceinline__ float key2f(unsigned k) {
    unsigned b = (k & 0x80000000u) ? (k ^ 0x80000000u) : ~k;
    return __uint_as_float(b);
}

// ---------------------------------------------------------------------------
// Kernel 1: per-row cross entropy + inline target-dtype detection.
// One warp per row, row (C<=1024 floats) in registers. HBM-bound (~22 us).
// NO global atomics (R7 showed hot-address atomics cost ~10 us here).
// ---------------------------------------------------------------------------
__global__ void __launch_bounds__(256)
ce_kernel(const float* __restrict__ x,
          const void* __restrict__ tgt,
          int N, int C)
{
    const int row  = blockIdx.x * 8 + (threadIdx.x >> 5);
    const int lane = threadIdx.x & 31;
    if (row >= N) return;

    const float4* rp = reinterpret_cast<const float4*>(x + (size_t)row * C);
    const int C4 = C >> 2;  // 250 for C=1000

    float4 v[8];
#pragma unroll
    for (int i = 0; i < 8; i++) {
        int c = lane + (i << 5);
        if (c < C4) v[i] = rp[c];
        else        v[i] = make_float4(-FLT_MAX, -FLT_MAX, -FLT_MAX, -FLT_MAX);
    }

    // Dtype probe (int64 targets in [0,C) have zero odd 32-bit words; L1-hot).
    const int* tw = reinterpret_cast<const int*>(tgt);
    int hiw = tw[2 * lane + 1];
    bool is64 = __all_sync(0xFFFFFFFFu, hiw == 0);

    float xt = 0.f;
    if (lane == 0) {
        long long t = is64 ? reinterpret_cast<const long long*>(tgt)[row]
                           : (long long)reinterpret_cast<const int*>(tgt)[row];
        if (t < 0)  t = 0;
        if (t >= C) t = C - 1;
        xt = x[(size_t)row * C + (int)t];
    }

    float m = -FLT_MAX;
#pragma unroll
    for (int i = 0; i < 8; i++)
        m = fmaxf(m, fmaxf(fmaxf(v[i].x, v[i].y), fmaxf(v[i].z, v[i].w)));
#pragma unroll
    for (int o = 16; o; o >>= 1)
        m = fmaxf(m, __shfl_xor_sync(0xFFFFFFFFu, m, o));

    float s0 = 0.f, s1 = 0.f, s2 = 0.f, s3 = 0.f;
#pragma unroll
    for (int i = 0; i < 8; i++) {
        s0 += __expf(v[i].x - m);
        s1 += __expf(v[i].y - m);
        s2 += __expf(v[i].z - m);
        s3 += __expf(v[i].w - m);
    }
    float s = (s0 + s1) + (s2 + s3);
#pragma unroll
    for (int o = 16; o; o >>= 1)
        s += __shfl_xor_sync(0xFFFFFFFFu, s, o);

    if (lane == 0)
        g_ce[row] = m + __logf(s) - xt;
}

// In-place 32x32 bit transpose (Hacker's Delight). Involution.
__device__ __forceinline__ void bit_transpose32(unsigned m[32])
{
#pragma unroll
    for (int st = 0; st < 5; st++) {
        const int j = 16 >> st;
        const unsigned msk = (st == 0) ? 0x0000FFFFu :
                             (st == 1) ? 0x00FF00FFu :
                             (st == 2) ? 0x0F0F0F0Fu :
                             (st == 3) ? 0x33333333u : 0x55555555u;
#pragma unroll
        for (int kk = 0; kk < 32; kk++) {
            if ((kk & j) == 0) {
                unsigned t2 = (m[kk] ^ (m[kk + j] >> j)) & msk;
                m[kk]     ^= t2;
                m[kk + j] ^= (t2 << j);
            }
        }
    }
}

// ---------------------------------------------------------------------------
// Kernel 2: single CTA, 1024 threads x 32 keys (loaded as 8 x float4).
// Transposed bitplanes; 8 rounds of 16-way MSB-first radix with PACKED
// warp reductions (2 x 16-bit counts per REDUX: warp sums <=1024, block
// sums <=32768 -> no carry). Exact tie semantics of sorted_desc[k].
// ---------------------------------------------------------------------------
__global__ void __launch_bounds__(1024)
select_mean_kernel(float* __restrict__ out, int N, int k)
{
    const int tid  = threadIdx.x;
    const int lane = tid & 31;
    const int wid  = tid >> 5;

    // Vectorized key load: slot i = 4*j + c  <->  idx = 4*(tid + (j<<10)) + c.
    // Warp loads 32 consecutive float4 = 512B contiguous. MLP = 8.
    const float4* ce4 = reinterpret_cast<const float4*>(g_ce);
    const int N4 = N >> 2;
    float4 vv[8];
#pragma unroll
    for (int j = 0; j < 8; j++) {
        int b = tid + (j << 10);
        if (b < N4) vv[j] = ce4[b];
        else        vv[j] = make_float4(-FLT_MAX, -FLT_MAX, -FLT_MAX, -FLT_MAX);
    }

    unsigned m[32];
#pragma unroll
    for (int j = 0; j < 8; j++) {
        m[4 * j + 0] = f2key(vv[j].x);
        m[4 * j + 1] = f2key(vv[j].y);
        m[4 * j + 2] = f2key(vv[j].z);
        m[4 * j + 3] = f2key(vv[j].w);
    }

    bit_transpose32(m);  // m[idx] = key-bit (31-idx) across slots; slot s at bit (31-s)

    __shared__ unsigned s_cnt[8 * 32];   // [packed-pair][warp]
    __shared__ int      s_sel;
    __shared__ float    s_fsum[32];

    unsigned amask  = 0xFFFFFFFFu;  // active slots
    unsigned lamkey = 0u;
    int rank = k;                   // consumed by tid 0 only

#pragma unroll
    for (int r = 0; r < 8; r++) {
        const unsigned p0 = m[4 * r + 0];
        const unsigned p1 = m[4 * r + 1];
        const unsigned p2 = m[4 * r + 2];
        const unsigned p3 = m[4 * r + 3];

        // 16 bucket masks -> per-thread counts, packed 2-per-word.
        unsigned c[16];
#pragma unroll
        for (int j = 0; j < 16; j++) {
            unsigned sel = amask;
            sel &= (j & 8) ? p0 : ~p0;
            sel &= (j & 4) ? p1 : ~p1;
            sel &= (j & 2) ? p2 : ~p2;
            sel &= (j & 1) ? p3 : ~p3;
            c[j] = (unsigned)__popc(sel);
        }
#pragma unroll
        for (int p = 0; p < 8; p++) {
            unsigned packed = c[2 * p] | (c[2 * p + 1] << 16);
            packed = __reduce_add_sync(0xFFFFFFFFu, packed);  // warp sum <=1024/field
            if (lane == p) s_cnt[p * 32 + wid] = packed;
        }
        __syncthreads();

        if (wid == 0) {
            unsigned t[8];
#pragma unroll
            for (int p = 0; p < 8; p++)
                t[p] = __reduce_add_sync(0xFFFFFFFFu, s_cnt[p * 32 + lane]);  // <=32768/field
            if (lane == 0) {
                int bc[16];
#pragma unroll
                for (int p = 0; p < 8; p++) {
                    bc[2 * p]     = (int)(t[p] & 0xFFFFu);
                    bc[2 * p + 1] = (int)(t[p] >> 16);
                }
                int chosen = 0;
                bool found = false;
#pragma unroll
                for (int q = 15; q >= 1; q--) {
                    if (!found) {
                        if (rank < bc[q]) { chosen = q; found = true; }
                        else               rank -= bc[q];
                    }
                }
                s_sel = chosen;
            }
        }
        __syncthreads();

        const int j = s_sel;
        unsigned sel = amask;
        sel &= (j & 8) ? p0 : ~p0;
        sel &= (j & 4) ? p1 : ~p1;
        sel &= (j & 2) ? p2 : ~p2;
        sel &= (j & 1) ? p3 : ~p3;
        amask = sel;
        lamkey |= ((unsigned)j) << (28 - 4 * r);
        __syncthreads();  // protect s_cnt / s_sel reuse next round
    }

    // ge mask from planes: slots with key >= lamkey (exact tie semantics).
    unsigned eq = 0xFFFFFFFFu, gt = 0u;
#pragma unroll
    for (int idx = 0; idx < 32; idx++) {
        if ((lamkey >> (31 - idx)) & 1u) {
            eq &= m[idx];
        } else {
            gt |= eq & m[idx];
            eq &= ~m[idx];
        }
    }
    const unsigned ge = gt | eq;

    // Transpose back to recover per-slot keys; masked sum via key2f (no reload).
    bit_transpose32(m);

    float sum = 0.f;
#pragma unroll
    for (int i = 0; i < 32; i++)
        if ((ge >> (31 - i)) & 1u) sum += key2f(m[i]);
#pragma unroll
    for (int o = 16; o; o >>= 1)
        sum += __shfl_xor_sync(0xFFFFFFFFu, sum, o);
    if (lane == 0) s_fsum[wid] = sum;
    __syncthreads();

    if (tid == 0) {
        double tot = 0.0;
#pragma unroll
        for (int w = 0; w < 32; w++) tot += (double)s_fsum[w];
        out[0] = (float)(tot / (double)N);
    }
}

// ---------------------------------------------------------------------------
extern "C" void kernel_launch(void* const* d_in, const int* in_sizes, int n_in,
                              void* d_out, int out_size)
{
    int li = 0, ti = 1;
    if (n_in >= 2 && in_sizes[1] > in_sizes[0]) { li = 1; ti = 0; }

    const float* x   = (const float*)d_in[li];
    const void*  tgt = d_in[ti];
    float* out = (float*)d_out;

    const int N = in_sizes[ti];            // 32768
    const int C = in_sizes[li] / N;        // 1000
    const int k = (int)((double)N * 0.3);  // 9830

    const int warps_per_block = 8;
    const int blocks = (N + warps_per_block - 1) / warps_per_block;
    ce_kernel<<<blocks, 256>>>(x, tgt, N, C);

    select_mean_kernel<<<1, 1024>>>(out, N, k);
}